// round 7
// baseline (speedup 1.0000x reference)
#include <cuda_runtime.h>
#include <cuda_bf16.h>
#include <math.h>
#include <stdint.h>

#define SS 512
#define BB 256
#define EE 256
#define HH 256
#define GG 1024   // 4*H
#define TT 32

// Scratch (device globals: allocation-free contract)
__device__ float g_gx[2][SS][BB][GG];        // pre-activations
__device__ float g_h[2][SS + 1][BB][HH];     // fp32 hidden states (for emit)
__device__ uint32_t g_hbf[2][2][BB][HH / 2]; // bf16x2 h exchange, double-buffered
__device__ float g_emit[BB][SS][TT];         // emission scores

// ---------------------------------------------------------------------------
__device__ __forceinline__ void mma_bf16(float d[4], const uint32_t a[4], const uint32_t b[2]) {
    asm volatile(
        "mma.sync.aligned.m16n8k16.row.col.f32.bf16.bf16.f32 "
        "{%0,%1,%2,%3}, {%4,%5,%6,%7}, {%8,%9}, {%0,%1,%2,%3};\n"
        : "+f"(d[0]), "+f"(d[1]), "+f"(d[2]), "+f"(d[3])
        : "r"(a[0]), "r"(a[1]), "r"(a[2]), "r"(a[3]), "r"(b[0]), "r"(b[1]));
}

__device__ __forceinline__ void ldsm_x4(uint32_t r[4], uint32_t addr) {
    asm volatile("ldmatrix.sync.aligned.m8n8.x4.shared.b16 {%0,%1,%2,%3}, [%4];"
        : "=r"(r[0]), "=r"(r[1]), "=r"(r[2]), "=r"(r[3]) : "r"(addr));
}

__device__ __forceinline__ uint32_t pack_bf16(float lo, float hi) {
    __nv_bfloat162 t = __floats2bfloat162_rn(lo, hi);
    return *(uint32_t*)&t;
}

__device__ __forceinline__ uint32_t smem_u32(const void* p) {
    uint32_t a;
    asm("{ .reg .u64 t; cvta.to.shared.u64 t, %1; cvt.u32.u64 %0, t; }"
        : "=r"(a) : "l"(p));
    return a;
}

#define CLUSTER_SYNC() do { \
    asm volatile("barrier.cluster.arrive.aligned;" ::: "memory"); \
    asm volatile("barrier.cluster.wait.aligned;" ::: "memory"); \
} while (0)

// ---------------------------------------------------------------------------
// Zero the bf16 h exchange buffers (must be zero at step 0 on every replay).
// ---------------------------------------------------------------------------
__global__ void init_kernel() {
    int idx = blockIdx.x * blockDim.x + threadIdx.x;   // 32768 uint4
    ((uint4*)g_hbf)[idx] = make_uint4(0u, 0u, 0u, 0u);
}

// ---------------------------------------------------------------------------
// Input projection with fused embedding gather (bf16 MMA + ldmatrix):
//   gx[dir][s][b][n] = sum_e embed[row][e] * W_ih[n][e] + b_ih[n] + b_hh[n]
// Block tile: 64 (batch rows at one s) x 128 (gate cols), K=256 smem-resident.
// Warp tile 16x64.
// ---------------------------------------------------------------------------
#define INP_SMEM ((64 + 128) * 132 * 4)

__global__ __launch_bounds__(256) void gemm_inproj_tc(
    const float* __restrict__ embed,
    const float* __restrict__ Wf, const float* __restrict__ Wb,
    const float* __restrict__ bih_f, const float* __restrict__ bhh_f,
    const float* __restrict__ bih_b, const float* __restrict__ bhh_b,
    const int* __restrict__ sent, const int* __restrict__ lens)
{
    extern __shared__ uint32_t smw[];
    uint32_t* au = smw;              // A: 64 rows x 132 words (bf16x2)
    uint32_t* wu = smw + 64 * 132;   // W: 128 cols x 132 words
    __shared__ int rowid[64];

    const int dir = blockIdx.z;
    const int m0 = blockIdx.x * 64;
    const int n0 = blockIdx.y * 128;
    const int s  = m0 >> 8;
    const int bf = m0 & 255;
    if (s >= lens[bf]) return;   // lengths sorted desc

    const int tid = threadIdx.x;
    if (tid < 64) {
        int b = bf + tid;
        int len = lens[b];
        int ss = (dir == 1 && s < len) ? (len - 1 - s) : s;
        rowid[tid] = sent[b * SS + ss];
    }
    __syncthreads();

    for (int idx = tid; idx < 64 * 64; idx += 256) {
        int r = idx >> 6, q4 = idx & 63;
        float4 v = *(const float4*)(embed + (size_t)rowid[r] * EE + q4 * 4);
        au[r * 132 + q4 * 2]     = pack_bf16(v.x, v.y);
        au[r * 132 + q4 * 2 + 1] = pack_bf16(v.z, v.w);
    }
    const float* __restrict__ W = dir ? Wb : Wf;
    for (int idx = tid; idx < 128 * 64; idx += 256) {
        int c = idx >> 6, q4 = idx & 63;
        float4 w = *(const float4*)(W + (size_t)(n0 + c) * EE + q4 * 4);
        wu[c * 132 + q4 * 2]     = pack_bf16(w.x, w.y);
        wu[c * 132 + q4 * 2 + 1] = pack_bf16(w.z, w.w);
    }
    __syncthreads();

    const int lane = tid & 31, wid = tid >> 5;
    const int wm = wid & 3, wn = wid >> 2;
    const int lr = lane >> 2, lc = lane & 3;

    float acc[8][4];
    #pragma unroll
    for (int i = 0; i < 8; i++)
        #pragma unroll
        for (int j = 0; j < 4; j++) acc[i][j] = 0.f;

    const uint32_t au_addr = smem_u32(au);
    const uint32_t wu_addr = smem_u32(wu);
    // A ldmatrix: lane -> row (m), k-half
    const uint32_t a_base = au_addr +
        (((wm * 16 + (lane & 15)) * 132 + ((lane >> 4) << 2)) << 2);
    // B ldmatrix: lane -> col (n), k-half
    const uint32_t b_base = wu_addr +
        ((((wn * 64) + (lane & 7) + ((lane >> 4) << 3)) * 132 + (((lane >> 3) & 1) << 2)) << 2);

    #pragma unroll 4
    for (int t = 0; t < 16; t++) {        // k = t*16
        uint32_t a[4];
        ldsm_x4(a, a_base + t * 32);
        #pragma unroll
        for (int p = 0; p < 4; p++) {
            uint32_t bb[4];
            ldsm_x4(bb, b_base + p * (16 * 132 * 4) + t * 32);
            mma_bf16(acc[p * 2],     a, bb);
            mma_bf16(acc[p * 2 + 1], a, bb + 2);
        }
    }

    const float* bi = dir ? bih_b : bih_f;
    const float* bh = dir ? bhh_b : bhh_f;
    float* gxp = &g_gx[dir][0][0][0];
    const int row = m0 + wm * 16 + lr;
    #pragma unroll
    for (int nf = 0; nf < 8; nf++) {
        int n = n0 + wn * 64 + nf * 8 + lc * 2;
        float b0v = bi[n] + bh[n];
        float b1v = bi[n + 1] + bh[n + 1];
        *(float2*)(gxp + (size_t)row * GG + n) =
            make_float2(acc[nf][0] + b0v, acc[nf][1] + b1v);
        *(float2*)(gxp + (size_t)(row + 8) * GG + n) =
            make_float2(acc[nf][2] + b0v, acc[nf][3] + b1v);
    }
}

// ---------------------------------------------------------------------------
// Persistent bidirectional LSTM: clusters of 8 CTAs per (dir, 32-batch tile),
// 128 CTAs total. Each CTA owns 128 gate cols (4 gates x 32 j).
// h exchange through gmem/L2 in bf16 (own 1KB slice written, full 8KB tile
// read back with __ldcg), ordered by the HW cluster barrier. Fragments via
// ldmatrix. W_hh stays in smem for all steps; cell state in registers.
// ---------------------------------------------------------------------------
#define LSTM_ST_WORDS (32 * 132)           // fp32 staging [32][132]
#define LSTM_WS_WORDS (128 * 132)          // bf16x2 weights [128 cols][132]
#define LSTM_HS_WORDS (32 * 132)           // bf16x2 h tile [32][132]
#define LSTM_SMEM ((LSTM_ST_WORDS + LSTM_WS_WORDS + LSTM_HS_WORDS) * 4)

__global__ __launch_bounds__(256, 1) __cluster_dims__(8, 1, 1)
void lstm_persist(
    const float* __restrict__ Whh_f, const float* __restrict__ Whh_b,
    const int* __restrict__ lens)
{
    extern __shared__ float smf[];
    float* st = smf;                                    // [32][132] fp32
    uint32_t* wsu = (uint32_t*)(smf + LSTM_ST_WORDS);   // [128][132] bf16x2
    uint32_t* hsu = wsu + LSTM_WS_WORDS;                // [32][132] bf16x2

    const int tid = threadIdx.x;
    const int jt  = blockIdx.x;          // cluster rank 0..7 -> j-cols jt*32..
    const int dir = blockIdx.y >> 3;
    const int mb  = blockIdx.y & 7;
    const int b0  = mb * 32;
    const int lenmax = lens[b0];         // same for whole cluster

    // Load bf16 weights once. Local col c (0..127): gate g=c>>5, j=jt*32+(c&31)
    const float* __restrict__ W = dir ? Whh_b : Whh_f;
    for (int idx = tid; idx < 128 * 64; idx += 256) {
        int c = idx >> 6, q4 = idx & 63;
        int n = ((c >> 5) << 8) + jt * 32 + (c & 31);
        float4 w = *(const float4*)(W + (size_t)n * HH + q4 * 4);
        wsu[c * 132 + q4 * 2]     = pack_bf16(w.x, w.y);
        wsu[c * 132 + q4 * 2 + 1] = pack_bf16(w.z, w.w);
    }

    const int lane = tid & 31, w = tid >> 5;
    const int lr = lane >> 2, lc = lane & 3;
    const int bl  = tid >> 3;            // epilogue batch row 0..31
    const int jl4 = (tid & 7) * 4;       // epilogue j group (4 cols)

    float creg[4] = {0.f, 0.f, 0.f, 0.f};

    const float* gxbase = &g_gx[dir][0][0][0];
    float* hbase = &g_h[dir][0][0][0];
    const uint32_t* hx_rd = &g_hbf[dir][0][0][0];       // phase via offset
    uint32_t* hx_wr = &g_hbf[dir][0][0][0];

    const uint32_t hs_addr = smem_u32(hsu);
    const uint32_t ws_addr = smem_u32(wsu);
    const uint32_t a_base = hs_addr +
        ((((lane & 15)) * 132 + ((lane >> 4) << 2)) << 2);
    const uint32_t b_base = ws_addr +
        ((((w * 16) + (lane & 7) + ((lane >> 4) << 3)) * 132 + (((lane >> 3) & 1) << 2)) << 2);

    // gmem read mapping: 4 uint4 per thread
    const int grow = tid >> 3;            // 0..31
    const int gq   = (tid & 7) * 4;       // uint4 index 0..28

    __syncthreads();   // weights ready (also before first barrier)

    for (int s = 0; s < lenmax; s++) {
        // ---- load h_prev tile (bf16) from gmem/L2 into smem ----
        {
            const uint4* src = (const uint4*)(hx_rd + (size_t)(s & 1) * (BB * 128)
                                              + (size_t)(b0 + grow) * 128) + gq;
            uint4* dst = (uint4*)(hsu + grow * 132 + gq * 4);
            #pragma unroll
            for (int q = 0; q < 4; q++) dst[q] = __ldcg(src + q);
        }

        // ---- prefetch this step's gx (independent; hides under MMA) ----
        const float* gxr = gxbase + (size_t)s * BB * GG
                         + (size_t)(b0 + bl) * GG + jt * 32 + jl4;
        float4 x0 = *(const float4*)(gxr);
        float4 x1 = *(const float4*)(gxr + 256);
        float4 x2 = *(const float4*)(gxr + 512);
        float4 x3 = *(const float4*)(gxr + 768);

        __syncthreads();

        float acc[2][2][4];
        #pragma unroll
        for (int mf = 0; mf < 2; mf++)
            #pragma unroll
            for (int nf = 0; nf < 2; nf++)
                #pragma unroll
                for (int q = 0; q < 4; q++) acc[mf][nf][q] = 0.f;

        #pragma unroll 4
        for (int t = 0; t < 16; t++) {    // k = t*16
            uint32_t a0[4], a1[4], bb[4];
            ldsm_x4(a0, a_base + t * 32);
            ldsm_x4(a1, a_base + 16 * 132 * 4 + t * 32);
            ldsm_x4(bb, b_base + t * 32);
            mma_bf16(acc[0][0], a0, bb);
            mma_bf16(acc[0][1], a0, bb + 2);
            mma_bf16(acc[1][0], a1, bb);
            mma_bf16(acc[1][1], a1, bb + 2);
        }

        // stage GEMM result: st[batch 0..31][local col 0..127]
        #pragma unroll
        for (int mf = 0; mf < 2; mf++)
            #pragma unroll
            for (int nf = 0; nf < 2; nf++) {
                int row = mf * 16 + lr, col = w * 16 + nf * 8 + lc * 2;
                *(float2*)&st[row * 132 + col] =
                    make_float2(acc[mf][nf][0], acc[mf][nf][1]);
                *(float2*)&st[(row + 8) * 132 + col] =
                    make_float2(acc[mf][nf][2], acc[mf][nf][3]);
            }
        __syncthreads();

        // epilogue: thread handles batch bl, j cols jl4..jl4+3
        float4 v0 = *(const float4*)&st[bl * 132 +       jl4];
        float4 v1 = *(const float4*)&st[bl * 132 +  32 + jl4];
        float4 v2 = *(const float4*)&st[bl * 132 +  64 + jl4];
        float4 v3 = *(const float4*)&st[bl * 132 +  96 + jl4];
        float gi[4] = {v0.x + x0.x, v0.y + x0.y, v0.z + x0.z, v0.w + x0.w};
        float gf[4] = {v1.x + x1.x, v1.y + x1.y, v1.z + x1.z, v1.w + x1.w};
        float gg[4] = {v2.x + x2.x, v2.y + x2.y, v2.z + x2.z, v2.w + x2.w};
        float go[4] = {v3.x + x3.x, v3.y + x3.y, v3.z + x3.z, v3.w + x3.w};

        float hn[4];
        #pragma unroll
        for (int k = 0; k < 4; k++) {
            float si = 1.f / (1.f + __expf(-gi[k]));
            float sf = 1.f / (1.f + __expf(-gf[k]));
            float so = 1.f / (1.f + __expf(-go[k]));
            float cn = sf * creg[k] + si * tanhf(gg[k]);
            creg[k] = cn;
            hn[k] = so * tanhf(cn);
        }

        // fp32 h to gmem for emit
        float* hd = hbase + (size_t)(s + 1) * BB * HH
                  + (size_t)(b0 + bl) * HH + jt * 32 + jl4;
        *(float4*)hd = make_float4(hn[0], hn[1], hn[2], hn[3]);

        // bf16 slice to the next-phase exchange buffer (own slice only)
        uint32_t* hw = hx_wr + (size_t)((s + 1) & 1) * (BB * 128)
                     + (size_t)(b0 + bl) * 128 + ((jt * 32 + jl4) >> 1);
        *(uint2*)hw = make_uint2(pack_bf16(hn[0], hn[1]), pack_bf16(hn[2], hn[3]));

        // cluster barrier: release our gmem writes, acquire peers'
        CLUSTER_SYNC();
    }
}

// ---------------------------------------------------------------------------
// emit via bf16 MMA (fp32 accumulate):
// emit[b][s][t] = b_out[t] + h_f[s].Wout[t][0:256] + h_b[len-1-s].Wout[t][256:512]
// ---------------------------------------------------------------------------
#define EMIT_SMEM (2 * 32 * 260 * 4)

__global__ __launch_bounds__(256) void emit_kernel(
    const float* __restrict__ Wout, const float* __restrict__ bout,
    const int* __restrict__ lens)
{
    extern __shared__ uint32_t es[];
    uint32_t* hbw = es;            // [32 s][260 words] bf16x2
    uint32_t* wbw = es + 32 * 260; // [32 t][260 words] bf16x2

    int b = blockIdx.x;
    int s0 = blockIdx.y * 32;
    int len = lens[b];
    if (s0 >= len) return;

    int tid = threadIdx.x;
    for (int idx = tid; idx < 32 * 128; idx += 256) {
        int sl = idx >> 7, q4 = idx & 127;
        int s = s0 + sl;
        float4 v = make_float4(0.f, 0.f, 0.f, 0.f);
        if (s < len) {
            int q = q4 * 4;
            if (q < 256) v = *(const float4*)&g_h[0][s + 1][b][q];
            else         v = *(const float4*)&g_h[1][len - s][b][q - 256];
        }
        hbw[sl * 260 + q4 * 2]     = pack_bf16(v.x, v.y);
        hbw[sl * 260 + q4 * 2 + 1] = pack_bf16(v.z, v.w);
    }
    for (int idx = tid; idx < 32 * 128; idx += 256) {
        int t = idx >> 7, q4 = idx & 127;
        float4 wv = *(const float4*)&Wout[t * 512 + q4 * 4];
        wbw[t * 260 + q4 * 2]     = pack_bf16(wv.x, wv.y);
        wbw[t * 260 + q4 * 2 + 1] = pack_bf16(wv.z, wv.w);
    }
    __syncthreads();

    const int lane = tid & 31, w = tid >> 5;
    const int m2 = w >> 2, n4 = w & 3;
    const int lr = lane >> 2, lc = lane & 3;

    float acc[4] = {0.f, 0.f, 0.f, 0.f};
    const int arow = (m2 * 16 + lr) * 260;
    const int brow = (n4 * 8 + lr) * 260;

    #pragma unroll 8
    for (int kc = 0; kc < 256; kc += 8) {
        uint32_t a[4], bb[2];
        a[0] = hbw[arow + kc + lc];
        a[1] = hbw[arow + 8 * 260 + kc + lc];
        a[2] = hbw[arow + kc + 4 + lc];
        a[3] = hbw[arow + 8 * 260 + kc + 4 + lc];
        bb[0] = wbw[brow + kc + lc];
        bb[1] = wbw[brow + kc + 4 + lc];
        mma_bf16(acc, a, bb);
    }

    int t = n4 * 8 + lc * 2;
    float b0v = bout[t], b1v = bout[t + 1];
    int r0 = s0 + m2 * 16 + lr;
    if (r0 < len)
        *(float2*)&g_emit[b][r0][t] = make_float2(acc[0] + b0v, acc[1] + b1v);
    if (r0 + 8 < len)
        *(float2*)&g_emit[b][r0 + 8][t] = make_float2(acc[2] + b0v, acc[3] + b1v);
}

// ---------------------------------------------------------------------------
// Per-batch CRF, one warp per b. Forward recursion with E=exp(trans) in
// registers, 4-way split dot chain, max rescale every 4 steps.
// ---------------------------------------------------------------------------
__global__ void crf_kernel(
    const float* __restrict__ trans,
    const int* __restrict__ tags,
    const int* __restrict__ lens,
    float* __restrict__ out)
{
    int b = blockIdx.x;
    int j = threadIdx.x;   // 0..31
    __shared__ float tr[32][33];

    int len = lens[b];
    for (int idx = j; idx < 1024; idx += 32)
        tr[idx >> 5][idx & 31] = trans[idx];
    __syncwarp();

    float E[32];
    #pragma unroll
    for (int i = 0; i < 32; i++) E[i] = __expf(tr[i][j]);

    const int* tg = tags + b * SS;
    const float* em = &g_emit[b][0][0];

    // real path score
    float rs = 0.f;
    for (int s = j; s < len; s += 32) {
        int t1 = tg[s];
        float v = em[s * 32 + t1];
        if (s > 0) v += tr[tg[s - 1]][t1];
        rs += v;
    }
    #pragma unroll
    for (int o = 16; o; o >>= 1) rs += __shfl_xor_sync(0xffffffffu, rs, o);

    // forward recursion
    float alpha = em[j];
    float M = alpha;
    #pragma unroll
    for (int o = 16; o; o >>= 1) M = fmaxf(M, __shfl_xor_sync(0xffffffffu, M, o));
    float beta = __expf(alpha - M);

    for (int s = 1; s < len; s++) {
        float d0 = 0.f, d1 = 0.f, d2 = 0.f, d3 = 0.f;
        #pragma unroll
        for (int i = 0; i < 32; i += 4) {
            d0 = fmaf(__shfl_sync(0xffffffffu, beta, i),     E[i],     d0);
            d1 = fmaf(__shfl_sync(0xffffffffu, beta, i + 1), E[i + 1], d1);
            d2 = fmaf(__shfl_sync(0xffffffffu, beta, i + 2), E[i + 2], d2);
            d3 = fmaf(__shfl_sync(0xffffffffu, beta, i + 3), E[i + 3], d3);
        }
        alpha = M + __logf((d0 + d1) + (d2 + d3)) + em[s * 32 + j];
        if ((s & 3) == 0) {
            float m2 = alpha;
            #pragma unroll
            for (int o = 16; o; o >>= 1)
                m2 = fmaxf(m2, __shfl_xor_sync(0xffffffffu, m2, o));
            M = m2;
        }
        beta = __expf(alpha - M);
    }

    float e = beta;
    #pragma unroll
    for (int o = 16; o; o >>= 1) e += __shfl_xor_sync(0xffffffffu, e, o);
    float logz = M + __logf(e);
    if (j == 0) out[b] = logz - rs;
}

// ---------------------------------------------------------------------------
extern "C" void kernel_launch(void* const* d_in, const int* in_sizes, int n_in,
                              void* d_out, int out_size)
{
    const float* embed = (const float*)d_in[0];
    const float* Wih_f = (const float*)d_in[1];
    const float* Whh_f = (const float*)d_in[2];
    const float* bih_f = (const float*)d_in[3];
    const float* bhh_f = (const float*)d_in[4];
    const float* Wih_b = (const float*)d_in[5];
    const float* Whh_b = (const float*)d_in[6];
    const float* bih_b = (const float*)d_in[7];
    const float* bhh_b = (const float*)d_in[8];
    const float* Wout  = (const float*)d_in[9];
    const float* bout  = (const float*)d_in[10];
    const float* trans = (const float*)d_in[11];
    const int* sent = (const int*)d_in[12];
    const int* tags = (const int*)d_in[13];
    const int* lens = (const int*)d_in[14];
    float* out = (float*)d_out;

    cudaFuncSetAttribute(gemm_inproj_tc,
                         cudaFuncAttributeMaxDynamicSharedMemorySize, INP_SMEM);
    cudaFuncSetAttribute(lstm_persist,
                         cudaFuncAttributeMaxDynamicSharedMemorySize, LSTM_SMEM);
    cudaFuncSetAttribute(emit_kernel,
                         cudaFuncAttributeMaxDynamicSharedMemorySize, EMIT_SMEM);

    init_kernel<<<128, 256>>>();

    dim3 g1(2048, 8, 2);
    gemm_inproj_tc<<<g1, 256, INP_SMEM>>>(embed, Wih_f, Wih_b,
                                          bih_f, bhh_f, bih_b, bhh_b, sent, lens);

    dim3 gl(8, 16);
    lstm_persist<<<gl, 256, LSTM_SMEM>>>(Whh_f, Whh_b, lens);

    dim3 ge(256, 16);
    emit_kernel<<<ge, 256, EMIT_SMEM>>>(Wout, bout, lens);

    crf_kernel<<<256, 32>>>(trans, tags, lens, out);
}

// round 8
// speedup vs baseline: 1.4783x; 1.4783x over previous
#include <cuda_runtime.h>
#include <cuda_bf16.h>
#include <math.h>
#include <stdint.h>

#define SS 512
#define BB 256
#define EE 256
#define HH 256
#define GG 1024   // 4*H
#define TT 32

// Scratch (device globals: allocation-free contract)
__device__ float g_gx[2][SS][BB][GG];        // pre-activations
__device__ float g_h[2][SS + 1][BB][HH];     // fp32 hidden states (for emit)
__device__ float g_emit[BB][SS][TT];         // emission scores

// ---------------------------------------------------------------------------
__device__ __forceinline__ void mma_bf16(float d[4], const uint32_t a[4], const uint32_t b[2]) {
    asm volatile(
        "mma.sync.aligned.m16n8k16.row.col.f32.bf16.bf16.f32 "
        "{%0,%1,%2,%3}, {%4,%5,%6,%7}, {%8,%9}, {%0,%1,%2,%3};\n"
        : "+f"(d[0]), "+f"(d[1]), "+f"(d[2]), "+f"(d[3])
        : "r"(a[0]), "r"(a[1]), "r"(a[2]), "r"(a[3]), "r"(b[0]), "r"(b[1]));
}

__device__ __forceinline__ void ldsm_x4(uint32_t r[4], uint32_t addr) {
    asm volatile("ldmatrix.sync.aligned.m8n8.x4.shared.b16 {%0,%1,%2,%3}, [%4];"
        : "=r"(r[0]), "=r"(r[1]), "=r"(r[2]), "=r"(r[3]) : "r"(addr));
}

__device__ __forceinline__ uint32_t pack_bf16(float lo, float hi) {
    __nv_bfloat162 t = __floats2bfloat162_rn(lo, hi);
    return *(uint32_t*)&t;
}

__device__ __forceinline__ uint32_t smem_u32(const void* p) {
    uint32_t a;
    asm("{ .reg .u64 t; cvta.to.shared.u64 t, %1; cvt.u32.u64 %0, t; }"
        : "=r"(a) : "l"(p));
    return a;
}

__device__ __forceinline__ float tanh_fast(float x) {
    float y;
    asm("tanh.approx.f32 %0, %1;" : "=f"(y) : "f"(x));
    return y;
}
__device__ __forceinline__ float sigmoid_fast(float x) {
    return fmaf(tanh_fast(0.5f * x), 0.5f, 0.5f);
}

#define CLUSTER_SYNC() do { \
    asm volatile("barrier.cluster.arrive.aligned;" ::: "memory"); \
    asm volatile("barrier.cluster.wait.aligned;" ::: "memory"); \
} while (0)

// ---------------------------------------------------------------------------
// Input projection with fused embedding gather (bf16 MMA + ldmatrix):
//   gx[dir][s][b][n] = sum_e embed[row][e] * W_ih[n][e] + b_ih[n] + b_hh[n]
// Block tile: 64 (batch rows at one s) x 128 (gate cols), K=256 smem-resident.
// ---------------------------------------------------------------------------
#define INP_SMEM ((64 + 128) * 132 * 4)

__global__ __launch_bounds__(256) void gemm_inproj_tc(
    const float* __restrict__ embed,
    const float* __restrict__ Wf, const float* __restrict__ Wb,
    const float* __restrict__ bih_f, const float* __restrict__ bhh_f,
    const float* __restrict__ bih_b, const float* __restrict__ bhh_b,
    const int* __restrict__ sent, const int* __restrict__ lens)
{
    extern __shared__ uint32_t smw[];
    uint32_t* au = smw;              // A: 64 rows x 132 words (bf16x2)
    uint32_t* wu = smw + 64 * 132;   // W: 128 cols x 132 words
    __shared__ int rowid[64];

    const int dir = blockIdx.z;
    const int m0 = blockIdx.x * 64;
    const int n0 = blockIdx.y * 128;
    const int s  = m0 >> 8;
    const int bf = m0 & 255;
    if (s >= lens[bf]) return;   // lengths sorted desc

    const int tid = threadIdx.x;
    if (tid < 64) {
        int b = bf + tid;
        int len = lens[b];
        int ss = (dir == 1 && s < len) ? (len - 1 - s) : s;
        rowid[tid] = sent[b * SS + ss];
    }
    __syncthreads();

    for (int idx = tid; idx < 64 * 64; idx += 256) {
        int r = idx >> 6, q4 = idx & 63;
        float4 v = *(const float4*)(embed + (size_t)rowid[r] * EE + q4 * 4);
        au[r * 132 + q4 * 2]     = pack_bf16(v.x, v.y);
        au[r * 132 + q4 * 2 + 1] = pack_bf16(v.z, v.w);
    }
    const float* __restrict__ W = dir ? Wb : Wf;
    for (int idx = tid; idx < 128 * 64; idx += 256) {
        int c = idx >> 6, q4 = idx & 63;
        float4 w = *(const float4*)(W + (size_t)(n0 + c) * EE + q4 * 4);
        wu[c * 132 + q4 * 2]     = pack_bf16(w.x, w.y);
        wu[c * 132 + q4 * 2 + 1] = pack_bf16(w.z, w.w);
    }
    __syncthreads();

    const int lane = tid & 31, wid = tid >> 5;
    const int wm = wid & 3, wn = wid >> 2;
    const int lr = lane >> 2, lc = lane & 3;

    float acc[8][4];
    #pragma unroll
    for (int i = 0; i < 8; i++)
        #pragma unroll
        for (int j = 0; j < 4; j++) acc[i][j] = 0.f;

    const uint32_t au_addr = smem_u32(au);
    const uint32_t wu_addr = smem_u32(wu);
    const uint32_t a_base = au_addr +
        (((wm * 16 + (lane & 15)) * 132 + ((lane >> 4) << 2)) << 2);
    const uint32_t b_base = wu_addr +
        ((((wn * 64) + (lane & 7) + ((lane >> 4) << 3)) * 132 + (((lane >> 3) & 1) << 2)) << 2);

    #pragma unroll 4
    for (int t = 0; t < 16; t++) {        // k = t*16
        uint32_t a[4];
        ldsm_x4(a, a_base + t * 32);
        #pragma unroll
        for (int p = 0; p < 4; p++) {
            uint32_t bb[4];
            ldsm_x4(bb, b_base + p * (16 * 132 * 4) + t * 32);
            mma_bf16(acc[p * 2],     a, bb);
            mma_bf16(acc[p * 2 + 1], a, bb + 2);
        }
    }

    const float* bi = dir ? bih_b : bih_f;
    const float* bh = dir ? bhh_b : bhh_f;
    float* gxp = &g_gx[dir][0][0][0];
    const int row = m0 + wm * 16 + lr;
    #pragma unroll
    for (int nf = 0; nf < 8; nf++) {
        int n = n0 + wn * 64 + nf * 8 + lc * 2;
        float b0v = bi[n] + bh[n];
        float b1v = bi[n + 1] + bh[n + 1];
        *(float2*)(gxp + (size_t)row * GG + n) =
            make_float2(acc[nf][0] + b0v, acc[nf][1] + b1v);
        *(float2*)(gxp + (size_t)(row + 8) * GG + n) =
            make_float2(acc[nf][2] + b0v, acc[nf][3] + b1v);
    }
}

// ---------------------------------------------------------------------------
// Persistent bidirectional LSTM: clusters of 8 CTAs per (dir, 16-batch tile),
// 256 CTAs total -> 2 independent clusters co-resident per SM (93 KB smem each)
// so their latency chains interleave. Each CTA owns 128 gate cols
// (4 gates x 32 j). h exchanged via DSMEM broadcast (double-buffered smem),
// fragments via ldmatrix, epilogue via tanh.approx. W_hh smem-resident.
// ---------------------------------------------------------------------------
#define LSTM_ST_WORDS (16 * 132)           // fp32 staging [16][132]
#define LSTM_WS_WORDS (128 * 132)          // bf16x2 weights [128 cols][132]
#define LSTM_HS_WORDS (2 * 16 * 132)       // bf16x2 h, double-buffered
#define LSTM_SMEM ((LSTM_ST_WORDS + LSTM_WS_WORDS + LSTM_HS_WORDS) * 4)

__global__ __launch_bounds__(256, 2) __cluster_dims__(8, 1, 1)
void lstm_persist(
    const float* __restrict__ Whh_f, const float* __restrict__ Whh_b,
    const int* __restrict__ lens)
{
    extern __shared__ float smf[];
    float* st = smf;                                    // [16][132] fp32
    uint32_t* wsu = (uint32_t*)(smf + LSTM_ST_WORDS);   // [128][132] bf16x2
    uint32_t* hsu = wsu + LSTM_WS_WORDS;                // [2][16][132] bf16x2

    const int tid = threadIdx.x;
    const int jt  = blockIdx.x;          // cluster rank 0..7 -> j-cols jt*32..
    const int dir = blockIdx.y >> 4;
    const int mb  = blockIdx.y & 15;
    const int b0  = mb * 16;
    const int lenmax = lens[b0];         // same for whole cluster

    // Load bf16 weights once. Local col c (0..127): gate g=c>>5, j=jt*32+(c&31)
    const float* __restrict__ W = dir ? Whh_b : Whh_f;
    for (int idx = tid; idx < 128 * 64; idx += 256) {
        int c = idx >> 6, q4 = idx & 63;
        int n = ((c >> 5) << 8) + jt * 32 + (c & 31);
        float4 w = *(const float4*)(W + (size_t)n * HH + q4 * 4);
        wsu[c * 132 + q4 * 2]     = pack_bf16(w.x, w.y);
        wsu[c * 132 + q4 * 2 + 1] = pack_bf16(w.z, w.w);
    }
    for (int idx = tid; idx < LSTM_HS_WORDS; idx += 256) hsu[idx] = 0u;

    const int lane = tid & 31, w = tid >> 5;
    const int lr = lane >> 2, lc = lane & 3;
    const int bl  = tid >> 4;            // epilogue batch row 0..15
    const int jl2 = (tid & 15) * 2;      // epilogue j pair

    float creg[2] = {0.f, 0.f};

    const float* gxbase = &g_gx[dir][0][0][0];
    float* hbase = &g_h[dir][0][0][0];
    const uint32_t hs_addr = smem_u32(hsu);
    const uint32_t ws_addr = smem_u32(wsu);
    // ldmatrix bases: A over h tile (16 rows), B over weights (warp's 16 cols)
    const uint32_t a_base = hs_addr +
        ((((lane & 15)) * 132 + ((lane >> 4) << 2)) << 2);
    const uint32_t b_base = ws_addr +
        ((((w * 16) + (lane & 7) + ((lane >> 4) << 3)) * 132 + (((lane >> 3) & 1) << 2)) << 2);

    __syncthreads();
    // peers must see our zeroed h buffers before their step-0 remote writes
    CLUSTER_SYNC();

    for (int s = 0; s < lenmax; s++) {
        // ---- prefetch this step's gx (independent; hides under MMA) ----
        const float* gxr = gxbase + (size_t)s * BB * GG
                         + (size_t)(b0 + bl) * GG + jt * 32 + jl2;
        float2 x0 = *(const float2*)(gxr);
        float2 x1 = *(const float2*)(gxr + 256);
        float2 x2 = *(const float2*)(gxr + 512);
        float2 x3 = *(const float2*)(gxr + 768);

        const uint32_t abase_s = a_base + (uint32_t)((s & 1) * (16 * 132 * 4));

        float acc[2][4];
        #pragma unroll
        for (int nf = 0; nf < 2; nf++)
            #pragma unroll
            for (int q = 0; q < 4; q++) acc[nf][q] = 0.f;

        #pragma unroll 8
        for (int t = 0; t < 16; t++) {    // k = t*16
            uint32_t a[4], bb[4];
            ldsm_x4(a, abase_s + t * 32);
            ldsm_x4(bb, b_base + t * 32);
            mma_bf16(acc[0], a, bb);
            mma_bf16(acc[1], a, bb + 2);
        }

        // stage GEMM result: st[batch 0..15][local col 0..127]
        #pragma unroll
        for (int nf = 0; nf < 2; nf++) {
            int col = w * 16 + nf * 8 + lc * 2;
            *(float2*)&st[lr * 132 + col] = make_float2(acc[nf][0], acc[nf][1]);
            *(float2*)&st[(lr + 8) * 132 + col] = make_float2(acc[nf][2], acc[nf][3]);
        }
        __syncthreads();

        // epilogue: thread handles batch bl, j cols jl2, jl2+1
        float2 v0 = *(const float2*)&st[bl * 132 +       jl2];
        float2 v1 = *(const float2*)&st[bl * 132 +  32 + jl2];
        float2 v2 = *(const float2*)&st[bl * 132 +  64 + jl2];
        float2 v3 = *(const float2*)&st[bl * 132 +  96 + jl2];
        float gi[2] = {v0.x + x0.x, v0.y + x0.y};
        float gf[2] = {v1.x + x1.x, v1.y + x1.y};
        float gg[2] = {v2.x + x2.x, v2.y + x2.y};
        float go[2] = {v3.x + x3.x, v3.y + x3.y};

        float hn[2];
        #pragma unroll
        for (int k = 0; k < 2; k++) {
            float si = sigmoid_fast(gi[k]);
            float sf = sigmoid_fast(gf[k]);
            float so = sigmoid_fast(go[k]);
            float cn = sf * creg[k] + si * tanh_fast(gg[k]);
            creg[k] = cn;
            hn[k] = so * tanh_fast(cn);
        }

        // fp32 h to gmem for emit (fire-and-forget)
        float* hd = hbase + (size_t)(s + 1) * BB * HH
                  + (size_t)(b0 + bl) * HH + jt * 32 + jl2;
        *(float2*)hd = make_float2(hn[0], hn[1]);

        // bf16 h word broadcast into all 8 cluster CTAs' next-phase buffer
        uint32_t pw = pack_bf16(hn[0], hn[1]);
        uint32_t woff = (uint32_t)(((s + 1) & 1) * (16 * 132)
                      + bl * 132 + jt * 16 + (jl2 >> 1));
        uint32_t baddr = hs_addr + woff * 4;
        #pragma unroll
        for (int r = 0; r < 8; r++) {
            uint32_t ra;
            asm("mapa.shared::cluster.u32 %0, %1, %2;" : "=r"(ra) : "r"(baddr), "r"(r));
            asm volatile("st.shared::cluster.b32 [%0], %1;" :: "r"(ra), "r"(pw) : "memory");
        }

        // release our writes / acquire peers' (also acts as CTA barrier)
        CLUSTER_SYNC();
    }
}

// ---------------------------------------------------------------------------
// emit via bf16 MMA (fp32 accumulate):
// emit[b][s][t] = b_out[t] + h_f[s].Wout[t][0:256] + h_b[len-1-s].Wout[t][256:512]
// ---------------------------------------------------------------------------
#define EMIT_SMEM (2 * 32 * 260 * 4)

__global__ __launch_bounds__(256) void emit_kernel(
    const float* __restrict__ Wout, const float* __restrict__ bout,
    const int* __restrict__ lens)
{
    extern __shared__ uint32_t es[];
    uint32_t* hbw = es;            // [32 s][260 words] bf16x2
    uint32_t* wbw = es + 32 * 260; // [32 t][260 words] bf16x2

    int b = blockIdx.x;
    int s0 = blockIdx.y * 32;
    int len = lens[b];
    if (s0 >= len) return;

    int tid = threadIdx.x;
    for (int idx = tid; idx < 32 * 128; idx += 256) {
        int sl = idx >> 7, q4 = idx & 127;
        int s = s0 + sl;
        float4 v = make_float4(0.f, 0.f, 0.f, 0.f);
        if (s < len) {
            int q = q4 * 4;
            if (q < 256) v = *(const float4*)&g_h[0][s + 1][b][q];
            else         v = *(const float4*)&g_h[1][len - s][b][q - 256];
        }
        hbw[sl * 260 + q4 * 2]     = pack_bf16(v.x, v.y);
        hbw[sl * 260 + q4 * 2 + 1] = pack_bf16(v.z, v.w);
    }
    for (int idx = tid; idx < 32 * 128; idx += 256) {
        int t = idx >> 7, q4 = idx & 127;
        float4 wv = *(const float4*)&Wout[t * 512 + q4 * 4];
        wbw[t * 260 + q4 * 2]     = pack_bf16(wv.x, wv.y);
        wbw[t * 260 + q4 * 2 + 1] = pack_bf16(wv.z, wv.w);
    }
    __syncthreads();

    const int lane = tid & 31, w = tid >> 5;
    const int m2 = w >> 2, n4 = w & 3;
    const int lr = lane >> 2, lc = lane & 3;

    float acc[4] = {0.f, 0.f, 0.f, 0.f};
    const int arow = (m2 * 16 + lr) * 260;
    const int brow = (n4 * 8 + lr) * 260;

    #pragma unroll 8
    for (int kc = 0; kc < 256; kc += 8) {
        uint32_t a[4], bb[2];
        a[0] = hbw[arow + kc + lc];
        a[1] = hbw[arow + 8 * 260 + kc + lc];
        a[2] = hbw[arow + kc + 4 + lc];
        a[3] = hbw[arow + 8 * 260 + kc + 4 + lc];
        bb[0] = wbw[brow + kc + lc];
        bb[1] = wbw[brow + kc + 4 + lc];
        mma_bf16(acc, a, bb);
    }

    int t = n4 * 8 + lc * 2;
    float b0v = bout[t], b1v = bout[t + 1];
    int r0 = s0 + m2 * 16 + lr;
    if (r0 < len)
        *(float2*)&g_emit[b][r0][t] = make_float2(acc[0] + b0v, acc[1] + b1v);
    if (r0 + 8 < len)
        *(float2*)&g_emit[b][r0 + 8][t] = make_float2(acc[2] + b0v, acc[3] + b1v);
}

// ---------------------------------------------------------------------------
// Per-batch CRF, one warp per b. Forward recursion with E=exp(trans) in
// registers, 4-way split dot chain, max rescale every 4 steps.
// ---------------------------------------------------------------------------
__global__ void crf_kernel(
    const float* __restrict__ trans,
    const int* __restrict__ tags,
    const int* __restrict__ lens,
    float* __restrict__ out)
{
    int b = blockIdx.x;
    int j = threadIdx.x;   // 0..31
    __shared__ float tr[32][33];

    int len = lens[b];
    for (int idx = j; idx < 1024; idx += 32)
        tr[idx >> 5][idx & 31] = trans[idx];
    __syncwarp();

    float E[32];
    #pragma unroll
    for (int i = 0; i < 32; i++) E[i] = __expf(tr[i][j]);

    const int* tg = tags + b * SS;
    const float* em = &g_emit[b][0][0];

    // real path score
    float rs = 0.f;
    for (int s = j; s < len; s += 32) {
        int t1 = tg[s];
        float v = em[s * 32 + t1];
        if (s > 0) v += tr[tg[s - 1]][t1];
        rs += v;
    }
    #pragma unroll
    for (int o = 16; o; o >>= 1) rs += __shfl_xor_sync(0xffffffffu, rs, o);

    // forward recursion
    float alpha = em[j];
    float M = alpha;
    #pragma unroll
    for (int o = 16; o; o >>= 1) M = fmaxf(M, __shfl_xor_sync(0xffffffffu, M, o));
    float beta = __expf(alpha - M);

    for (int s = 1; s < len; s++) {
        float d0 = 0.f, d1 = 0.f, d2 = 0.f, d3 = 0.f;
        #pragma unroll
        for (int i = 0; i < 32; i += 4) {
            d0 = fmaf(__shfl_sync(0xffffffffu, beta, i),     E[i],     d0);
            d1 = fmaf(__shfl_sync(0xffffffffu, beta, i + 1), E[i + 1], d1);
            d2 = fmaf(__shfl_sync(0xffffffffu, beta, i + 2), E[i + 2], d2);
            d3 = fmaf(__shfl_sync(0xffffffffu, beta, i + 3), E[i + 3], d3);
        }
        alpha = M + __logf((d0 + d1) + (d2 + d3)) + em[s * 32 + j];
        if ((s & 3) == 0) {
            float m2 = alpha;
            #pragma unroll
            for (int o = 16; o; o >>= 1)
                m2 = fmaxf(m2, __shfl_xor_sync(0xffffffffu, m2, o));
            M = m2;
        }
        beta = __expf(alpha - M);
    }

    float e = beta;
    #pragma unroll
    for (int o = 16; o; o >>= 1) e += __shfl_xor_sync(0xffffffffu, e, o);
    float logz = M + __logf(e);
    if (j == 0) out[b] = logz - rs;
}

// ---------------------------------------------------------------------------
extern "C" void kernel_launch(void* const* d_in, const int* in_sizes, int n_in,
                              void* d_out, int out_size)
{
    const float* embed = (const float*)d_in[0];
    const float* Wih_f = (const float*)d_in[1];
    const float* Whh_f = (const float*)d_in[2];
    const float* bih_f = (const float*)d_in[3];
    const float* bhh_f = (const float*)d_in[4];
    const float* Wih_b = (const float*)d_in[5];
    const float* Whh_b = (const float*)d_in[6];
    const float* bih_b = (const float*)d_in[7];
    const float* bhh_b = (const float*)d_in[8];
    const float* Wout  = (const float*)d_in[9];
    const float* bout  = (const float*)d_in[10];
    const float* trans = (const float*)d_in[11];
    const int* sent = (const int*)d_in[12];
    const int* tags = (const int*)d_in[13];
    const int* lens = (const int*)d_in[14];
    float* out = (float*)d_out;

    cudaFuncSetAttribute(gemm_inproj_tc,
                         cudaFuncAttributeMaxDynamicSharedMemorySize, INP_SMEM);
    cudaFuncSetAttribute(lstm_persist,
                         cudaFuncAttributeMaxDynamicSharedMemorySize, LSTM_SMEM);
    cudaFuncSetAttribute(emit_kernel,
                         cudaFuncAttributeMaxDynamicSharedMemorySize, EMIT_SMEM);

    dim3 g1(2048, 8, 2);
    gemm_inproj_tc<<<g1, 256, INP_SMEM>>>(embed, Wih_f, Wih_b,
                                          bih_f, bhh_f, bih_b, bhh_b, sent, lens);

    dim3 gl(8, 32);
    lstm_persist<<<gl, 256, LSTM_SMEM>>>(Whh_f, Whh_b, lens);

    dim3 ge(256, 16);
    emit_kernel<<<ge, 256, EMIT_SMEM>>>(Wout, bout, lens);

    crf_kernel<<<256, 32>>>(trans, tags, lens, out);
}